// round 1
// baseline (speedup 1.0000x reference)
#include <cuda_runtime.h>
#include <math.h>

// ANI AEV computer.
// M=32 molecules, A=48 atoms, S=4 species.
// Radial: 16 ShfR, cutoff RCR=5.2 -> 4*16 = 64 channels.
// Angular: 4 ShfA x 8 ShfZ, cutoff RCA=3.5 -> 10*32 = 320 channels.
// Output: (M, A, 384) float32.

#define MM 32
#define AA 48
#define SS 4
#define NSHFR 16
#define NSHFA 4
#define NSHFZ 8
#define RAD_SUB 16
#define ANG_SUB 32
#define NPAIRS_SP 10
#define OUT_PER_ATOM (SS * RAD_SUB + NPAIRS_SP * ANG_SUB)  // 384
#define RCR_F 5.2f
#define RCA_F 3.5f
#define NTHREADS 128

__global__ __launch_bounds__(NTHREADS)
void aev_kernel(const float* __restrict__ coords,
                const float* __restrict__ EtaR,
                const float* __restrict__ ShfR,
                const float* __restrict__ EtaA,
                const float* __restrict__ Zeta,
                const float* __restrict__ ShfA,
                const float* __restrict__ ShfZ,
                const int*   __restrict__ species,
                float*       __restrict__ out)
{
    const int m  = blockIdx.x / AA;
    const int ci = blockIdx.x % AA;
    const int tid = threadIdx.x;

    __shared__ float sx[AA], sy[AA], sz[AA];
    __shared__ int   ssp[AA];
    __shared__ float acc[OUT_PER_ATOM];
    __shared__ float shfR[NSHFR], shfA[NSHFA], cosZ[NSHFZ], sinZ[NSHFZ];
    __shared__ float s_etaR, s_etaA, s_zeta;
    __shared__ int   nnb;
    __shared__ int   nbj[AA];
    __shared__ float nbd[AA], nbx[AA], nby[AA], nbz[AA];

    if (tid < AA) {
        sx[tid]  = coords[(m * AA + tid) * 3 + 0];
        sy[tid]  = coords[(m * AA + tid) * 3 + 1];
        sz[tid]  = coords[(m * AA + tid) * 3 + 2];
        ssp[tid] = species[m * AA + tid];
    }
    if (tid < NSHFR) shfR[tid] = ShfR[tid];
    if (tid < NSHFA) shfA[tid] = ShfA[tid];
    if (tid < NSHFZ) {
        float s = ShfZ[tid];
        cosZ[tid] = cosf(s);
        sinZ[tid] = sinf(s);
    }
    if (tid == 0) {
        s_etaR = EtaR[0];
        s_etaA = EtaA[0];
        s_zeta = Zeta[0];
        nnb = 0;
    }
    for (int c = tid; c < OUT_PER_ATOM; c += NTHREADS) acc[c] = 0.0f;
    __syncthreads();

    const float cxi = sx[ci], cyi = sy[ci], czi = sz[ci];

    // ---- radial contributions to atom ci + angular neighbor list build ----
    if (tid < AA && tid != ci) {
        const int j = tid;
        const float dx = sx[j] - cxi;
        const float dy = sy[j] - cyi;
        const float dz = sz[j] - czi;
        const float d  = sqrtf(dx * dx + dy * dy + dz * dz);

        if (d <= RCR_F) {
            const float fc   = 0.5f * __cosf(d * (float)(M_PI / 5.2)) + 0.5f;
            const float base = 0.25f * fc;
            const int   off  = ssp[j] * RAD_SUB;
            const float eR   = s_etaR;
            #pragma unroll
            for (int t = 0; t < NSHFR; t++) {
                const float x = d - shfR[t];
                atomicAdd(&acc[off + t], base * __expf(-eR * x * x));
            }
        }
        if (d <= RCA_F) {
            const int slot = atomicAdd(&nnb, 1);
            nbj[slot] = j;
            nbd[slot] = d;
            nbx[slot] = dx;
            nby[slot] = dy;
            nbz[slot] = dz;
        }
    }
    __syncthreads();

    // ---- angular contributions: all unordered pairs of neighbors ----
    const int n = nnb;
    const int npair = n * (n - 1) / 2;
    const float etaA = s_etaA;
    const float zeta = s_zeta;
    const bool  z32  = (zeta == 32.0f);

    for (int p = tid; p < npair; p += NTHREADS) {
        // decode p -> (a, b), a < b   (linear scan; n <= 47)
        int a = 0, rem = p;
        while (rem >= n - 1 - a) { rem -= n - 1 - a; a++; }
        const int b = a + 1 + rem;

        const float d1 = nbd[a], d2 = nbd[b];
        const float inv = 1.0f / (fmaxf(d1, 1e-8f) * fmaxf(d2, 1e-8f));
        const float dot = nbx[a] * nbx[b] + nby[a] * nby[b] + nbz[a] * nbz[b];
        const float c   = 0.95f * dot * inv;
        const float sn  = sqrtf(fmaxf(1.0f - c * c, 0.0f));

        const float fc1 = 0.5f * __cosf(d1 * (float)(M_PI / 3.5)) + 0.5f;
        const float fc2 = 0.5f * __cosf(d2 * (float)(M_PI / 3.5)) + 0.5f;
        const float fcj2 = 2.0f * fc1 * fc2;
        const float dm = 0.5f * (d1 + d2);

        const int sa = ssp[nbj[a]];
        const int sb = ssp[nbj[b]];
        const int lo = min(sa, sb);
        const int hi = max(sa, sb);
        const int pidx = lo * SS - (lo * (lo - 1)) / 2 + (hi - lo);

        float* dst = &acc[SS * RAD_SUB + pidx * ANG_SUB];

        #pragma unroll
        for (int ia = 0; ia < NSHFA; ia++) {
            const float x  = dm - shfA[ia];
            const float f2 = __expf(-etaA * x * x) * fcj2;
            #pragma unroll
            for (int iz = 0; iz < NSHFZ; iz++) {
                // cos(arccos(c) - ShfZ) = c*cosZ + sqrt(1-c^2)*sinZ
                const float cz = 0.5f * (1.0f + c * cosZ[iz] + sn * sinZ[iz]);
                float f1;
                if (z32) {
                    float t = cz * cz;  // ^2
                    t *= t;             // ^4
                    t *= t;             // ^8
                    t *= t;             // ^16
                    t *= t;             // ^32
                    f1 = t;
                } else {
                    f1 = __powf(cz, zeta);
                }
                atomicAdd(&dst[ia * NSHFZ + iz], f1 * f2);
            }
        }
    }
    __syncthreads();

    // ---- write out ----
    float* o = out + (size_t)(m * AA + ci) * OUT_PER_ATOM;
    for (int c = tid; c < OUT_PER_ATOM; c += NTHREADS) o[c] = acc[c];
}

extern "C" void kernel_launch(void* const* d_in, const int* in_sizes, int n_in,
                              void* d_out, int out_size)
{
    const float* coords  = (const float*)d_in[0];
    const float* EtaR    = (const float*)d_in[1];
    const float* ShfR    = (const float*)d_in[2];
    const float* EtaA    = (const float*)d_in[3];
    const float* Zeta    = (const float*)d_in[4];
    const float* ShfA    = (const float*)d_in[5];
    const float* ShfZ    = (const float*)d_in[6];
    const int*   species = (const int*)d_in[7];
    float* out = (float*)d_out;

    aev_kernel<<<MM * AA, NTHREADS>>>(coords, EtaR, ShfR, EtaA, Zeta,
                                      ShfA, ShfZ, species, out);
}

// round 2
// speedup vs baseline: 4.1594x; 4.1594x over previous
#include <cuda_runtime.h>
#include <math.h>

// ANI AEV computer.
// M=32 molecules, A=48 atoms, S=4 species.
// Radial: 16 ShfR, cutoff RCR=5.2 -> 4*16 = 64 channels.
// Angular: 4 ShfA x 8 ShfZ, cutoff RCA=3.5 -> 10*32 = 320 channels.
// Output: (M, A, 384) float32.
//
// R1: lane-staggered shared atomics -> intra-warp conflict-free accumulation.

#define MM 32
#define AA 48
#define SS 4
#define NSHFR 16
#define NSHFA 4
#define NSHFZ 8
#define RAD_SUB 16
#define ANG_SUB 32
#define NPAIRS_SP 10
#define OUT_PER_ATOM (SS * RAD_SUB + NPAIRS_SP * ANG_SUB)  // 384
#define RCR_F 5.2f
#define RCA_F 3.5f
#define NTHREADS 128

__global__ __launch_bounds__(NTHREADS)
void aev_kernel(const float* __restrict__ coords,
                const float* __restrict__ EtaR,
                const float* __restrict__ ShfR,
                const float* __restrict__ EtaA,
                const float* __restrict__ Zeta,
                const float* __restrict__ ShfA,
                const float* __restrict__ ShfZ,
                const int*   __restrict__ species,
                float*       __restrict__ out)
{
    const int m   = blockIdx.x / AA;
    const int ci  = blockIdx.x % AA;
    const int tid = threadIdx.x;
    const int lane = tid & 31;

    __shared__ float sx[AA], sy[AA], sz[AA];
    __shared__ int   ssp[AA];
    __shared__ float acc[OUT_PER_ATOM];
    __shared__ float shfR[NSHFR], shfA[NSHFA], cosZ[NSHFZ], sinZ[NSHFZ];
    __shared__ float s_etaR, s_etaA, s_zeta;
    __shared__ int   nnb;
    __shared__ int   nbj[AA];
    __shared__ float nbd[AA], nbx[AA], nby[AA], nbz[AA];

    if (tid < AA) {
        sx[tid]  = coords[(m * AA + tid) * 3 + 0];
        sy[tid]  = coords[(m * AA + tid) * 3 + 1];
        sz[tid]  = coords[(m * AA + tid) * 3 + 2];
        ssp[tid] = species[m * AA + tid];
    }
    if (tid < NSHFR) shfR[tid] = ShfR[tid];
    if (tid < NSHFA) shfA[tid] = ShfA[tid];
    if (tid < NSHFZ) {
        float s = ShfZ[tid];
        cosZ[tid] = cosf(s);
        sinZ[tid] = sinf(s);
    }
    if (tid == 0) {
        s_etaR = EtaR[0];
        s_etaA = EtaA[0];
        s_zeta = Zeta[0];
        nnb = 0;
    }
    for (int c = tid; c < OUT_PER_ATOM; c += NTHREADS) acc[c] = 0.0f;
    __syncthreads();

    const float cxi = sx[ci], cyi = sy[ci], czi = sz[ci];

    // ---- radial contributions to atom ci + angular neighbor list build ----
    if (tid < AA && tid != ci) {
        const int j = tid;
        const float dx = sx[j] - cxi;
        const float dy = sy[j] - cyi;
        const float dz = sz[j] - czi;
        const float d  = sqrtf(dx * dx + dy * dy + dz * dz);

        if (d <= RCR_F) {
            const float fc   = 0.5f * __cosf(d * (float)(M_PI / 5.2)) + 0.5f;
            const float base = 0.25f * fc;
            const int   off  = ssp[j] * RAD_SUB;
            const float eR   = s_etaR;
            // lane-staggered order: lanes with the same species hit different
            // shifts at every step -> (almost) conflict-free shared atomics.
            #pragma unroll
            for (int k = 0; k < NSHFR; k++) {
                const int t = (k + lane) & (NSHFR - 1);
                const float x = d - shfR[t];
                atomicAdd(&acc[off + t], base * __expf(-eR * x * x));
            }
        }
        if (d <= RCA_F) {
            const int slot = atomicAdd(&nnb, 1);
            nbj[slot] = j;
            nbd[slot] = d;
            nbx[slot] = dx;
            nby[slot] = dy;
            nbz[slot] = dz;
        }
    }
    __syncthreads();

    // ---- angular contributions: all unordered pairs of neighbors ----
    const int n = nnb;
    const int npair = n * (n - 1) / 2;
    const float etaA = s_etaA;
    const float zeta = s_zeta;
    const bool  z32  = (zeta == 32.0f);
    const int   rot_a = (lane >> 3) & 3;

    for (int p = tid; p < npair; p += NTHREADS) {
        // decode p -> (a, b), a < b   (linear scan; n <= 47)
        int a = 0, rem = p;
        while (rem >= n - 1 - a) { rem -= n - 1 - a; a++; }
        const int b = a + 1 + rem;

        const float d1 = nbd[a], d2 = nbd[b];
        const float inv = __fdividef(1.0f, fmaxf(d1, 1e-8f) * fmaxf(d2, 1e-8f));
        const float dot = nbx[a] * nbx[b] + nby[a] * nby[b] + nbz[a] * nbz[b];
        const float c   = 0.95f * dot * inv;
        const float sn  = sqrtf(fmaxf(1.0f - c * c, 0.0f));

        const float fc1 = 0.5f * __cosf(d1 * (float)(M_PI / 3.5)) + 0.5f;
        const float fc2 = 0.5f * __cosf(d2 * (float)(M_PI / 3.5)) + 0.5f;
        const float fcj2 = 2.0f * fc1 * fc2;
        const float dm = 0.5f * (d1 + d2);

        const int sa = ssp[nbj[a]];
        const int sb = ssp[nbj[b]];
        const int lo = min(sa, sb);
        const int hi = max(sa, sb);
        const int pidx = lo * SS - (lo * (lo - 1)) / 2 + (hi - lo);

        float* dst = &acc[SS * RAD_SUB + pidx * ANG_SUB];

        // lane-staggered (ia, iz) ordering: two lanes collide on the same
        // channel at the same step only if lane == lane' (mod 32) -> never
        // within a warp.
        #pragma unroll
        for (int ja = 0; ja < NSHFA; ja++) {
            const int ia = (ja + rot_a) & (NSHFA - 1);
            const float x  = dm - shfA[ia];
            const float f2 = __expf(-etaA * x * x) * fcj2;
            #pragma unroll
            for (int jz = 0; jz < NSHFZ; jz++) {
                const int iz = (jz + lane) & (NSHFZ - 1);
                // cos(arccos(c) - ShfZ) = c*cosZ + sqrt(1-c^2)*sinZ
                const float cz = 0.5f * (1.0f + c * cosZ[iz] + sn * sinZ[iz]);
                float f1;
                if (z32) {
                    float t = cz * cz;  // ^2
                    t *= t;             // ^4
                    t *= t;             // ^8
                    t *= t;             // ^16
                    t *= t;             // ^32
                    f1 = t;
                } else {
                    f1 = __powf(cz, zeta);
                }
                atomicAdd(&dst[ia * NSHFZ + iz], f1 * f2);
            }
        }
    }
    __syncthreads();

    // ---- write out ----
    float* o = out + (size_t)(m * AA + ci) * OUT_PER_ATOM;
    for (int c = tid; c < OUT_PER_ATOM; c += NTHREADS) o[c] = acc[c];
}

extern "C" void kernel_launch(void* const* d_in, const int* in_sizes, int n_in,
                              void* d_out, int out_size)
{
    const float* coords  = (const float*)d_in[0];
    const float* EtaR    = (const float*)d_in[1];
    const float* ShfR    = (const float*)d_in[2];
    const float* EtaA    = (const float*)d_in[3];
    const float* Zeta    = (const float*)d_in[4];
    const float* ShfA    = (const float*)d_in[5];
    const float* ShfZ    = (const float*)d_in[6];
    const int*   species = (const int*)d_in[7];
    float* out = (float*)d_out;

    aev_kernel<<<MM * AA, NTHREADS>>>(coords, EtaR, ShfR, EtaA, Zeta,
                                      ShfA, ShfZ, species, out);
}